// round 13
// baseline (speedup 1.0000x reference)
#include <cuda_runtime.h>
#include <cstdint>

#define B_  16
#define L_  64
#define F_  60
#define D_  256
#define U_  600
#define V_  10000
#define E_  7
#define NEGF (-1e9f)

// Scratch (device globals)
__device__ float g_wn[1024 * 256];
__device__ float g_un[600 * 256];
__device__ float g_sim[2 * 1024 * 600];      // two K-halves, summed in phaseB staging
__device__ uint4 g_segB[7 * V_ * 2];         // length-bucketed vocab
__device__ int   g_cnt[8];                   // bucket counts (zeroed by phaseB epilogue)
__device__ unsigned long long g_keys[16];
__device__ unsigned g_done;

// ---- f32x2 helpers (gemm) ----
__device__ __forceinline__ void ffma2(unsigned long long& d, unsigned long long a, unsigned long long b) {
    asm("fma.rn.f32x2 %0, %1, %2, %0;" : "+l"(d) : "l"(a), "l"(b));
}
__device__ __forceinline__ unsigned long long pk2dup(float a) {
    unsigned long long r; unsigned ai = __float_as_uint(a);
    asm("mov.b64 %0, {%1, %1};" : "=l"(r) : "r"(ai));
    return r;
}
__device__ __forceinline__ float2 unpk2(unsigned long long a) {
    unsigned lo, hi;
    asm("mov.b64 {%0, %1}, %2;" : "=r"(lo), "=r"(hi) : "l"(a));
    return make_float2(__uint_as_float(lo), __uint_as_float(hi));
}

__device__ __forceinline__ unsigned f2mono(float f) {
    unsigned b = __float_as_uint(f);
    return (b & 0x80000000u) ? ~b : (b | 0x80000000u);
}
__device__ __forceinline__ unsigned long long pack_key(float s, int f, int v) {
    return ((unsigned long long)f2mono(s) << 23)
         | ((unsigned long long)(511 - f) << 14)
         | (unsigned long long)(16383 - v);
}

// ---------------------------------------------------------------------------
// Kernel 1 (setup):
//   blocks   0..39  : vocab bucketing FIRST (atomics overlap embed compute)
//   blocks  40..295 : word rows  (256*4 = 1024)
//   blocks 296..445 : unit rows  (150*4 = 600)
// Embed uses an explicit 12-deep W prefetch buffer to keep loads in flight.
// ---------------------------------------------------------------------------
#define PBK_ 40
#define WB_ 256
#define UB_ 150
#define SETUP_GRID (PBK_ + WB_ + UB_)   // 446

__global__ void __launch_bounds__(256) k_setup(const float* __restrict__ x,
                                               const float* __restrict__ uf,
                                               const float* __restrict__ W,
                                               const int* __restrict__ segs,
                                               const int* __restrict__ vlen) {
    int blk = blockIdx.x;
    int d = threadIdx.x;               // 0..255
    if (blk >= PBK_) {
        // ---- embed 4 rows/block, batched W prefetch ----
        __shared__ float feat[4 * F_];
        __shared__ float spart[4 * 8];
        __shared__ float sinv[4];
        int eb = blk - PBK_;
        bool isWord = eb < WB_;
        int r0 = isWord ? eb * 4 : (eb - WB_) * 4;
        const float* src = isWord ? (x + r0 * F_) : (uf + r0 * F_);
        float* dst = isWord ? (g_wn + r0 * D_) : (g_un + r0 * D_);
        if (d < 60) ((float4*)feat)[d] = ((const float4*)src)[d];  // 240 floats
        float val[4] = {0.f, 0.f, 0.f, 0.f};
        float wv[12];
        // prologue: first batch of W loads in flight before sync
        #pragma unroll
        for (int i = 0; i < 12; i++) wv[i] = __ldg(&W[i * D_ + d]);
        __syncthreads();
        #pragma unroll
        for (int f0 = 0; f0 < 60; f0 += 12) {
            float cur[12];
            #pragma unroll
            for (int i = 0; i < 12; i++) cur[i] = wv[i];
            if (f0 + 12 < 60) {
                #pragma unroll
                for (int i = 0; i < 12; i++) wv[i] = __ldg(&W[(f0 + 12 + i) * D_ + d]);
            }
            #pragma unroll
            for (int i = 0; i < 12; i++) {
                float w = cur[i];
                #pragma unroll
                for (int r = 0; r < 4; r++) val[r] = fmaf(feat[r * F_ + f0 + i], w, val[r]);
            }
        }
        int lane = d & 31, w = d >> 5;
        #pragma unroll
        for (int r = 0; r < 4; r++) {
            float q = val[r] * val[r];
            #pragma unroll
            for (int o = 16; o; o >>= 1) q += __shfl_down_sync(0xffffffffu, q, o);
            if (lane == 0) spart[r * 8 + w] = q;
        }
        __syncthreads();
        if (d < 4) {
            float s = 0.f;
            #pragma unroll
            for (int i = 0; i < 8; i++) s += spart[d * 8 + i];
            sinv[d] = 1.0f / (sqrtf(s) + 1e-8f);
        }
        __syncthreads();
        #pragma unroll
        for (int r = 0; r < 4; r++) dst[r * D_ + d] = val[r] * sinv[r];
    } else {
        // ---- bucket vocab by length: block-aggregated atomics ----
        __shared__ int blkCnt[8];
        __shared__ int blkBase[8];
        int pb = blk;
        int v = pb * 256 + d;
        bool act = v < V_;
        if (d < 8) blkCnt[d] = 0;
        __syncthreads();
        int len = act ? vlen[v] : 11;
        int idx = act ? (len - 4) : 7;
        int lane = d & 31;
        unsigned mask = __match_any_sync(0xffffffffu, idx);
        int leader = __ffs(mask) - 1;
        int prior = __popc(mask & ((1u << lane) - 1));
        int wbase = 0;
        if (lane == leader) wbase = atomicAdd(&blkCnt[idx], __popc(mask));
        wbase = __shfl_sync(mask, wbase, leader);
        int local = wbase + prior;
        __syncthreads();
        if (d < 8) blkBase[d] = atomicAdd(&g_cnt[d], blkCnt[d]);
        __syncthreads();
        if (act) {
            unsigned w[5];
            #pragma unroll
            for (int p = 0; p < 5; p++) {
                unsigned lo = (unsigned)segs[v * 10 + 2 * p];
                unsigned hi = (unsigned)segs[v * 10 + 2 * p + 1];
                w[p] = (lo & 0xFFFFu) | (hi << 16);
            }
            if (len <= 7) w[3] = (w[3] & 0xFFFFu) | ((unsigned)v << 16);
            int slot = idx * V_ + blkBase[idx] + local;
            g_segB[slot * 2]     = make_uint4(w[0], w[1], w[2], w[3]);
            g_segB[slot * 2 + 1] = make_uint4(w[4], (unsigned)v, 0u, 0u);
        }
        if (pb == 0) {
            if (d >= 32 && d < 48) g_keys[d - 32] = pack_key(NEGF, 0, 0);
            if (d == 63) g_done = 0u;
        }
    }
}

// ---------------------------------------------------------------------------
// Kernel 2: sim = wn @ un^T.  128x64 tile, 256 threads, 8x4 per-thread
// register tile, FFMA2.  K split in halves.  grid = (10, 8, 2) = 160 CTAs.
// (unchanged from R11 — measured near its smem-BW bound)
// ---------------------------------------------------------------------------
__global__ void __launch_bounds__(256) k_sim_gemm() {
    __shared__ float As[16][128];
    __shared__ float Bs[16][64];
    int tid = threadIdx.x;
    int n0 = blockIdx.x * 64;
    int m0 = blockIdx.y * 128;
    int kz = blockIdx.z;
    float* dst = g_sim + kz * (1024 * 600);
    int tx = tid & 15;
    int ty = tid >> 4;
    int am = tid >> 1;
    int ak = (tid & 1) * 8;
    int bn = tid >> 2;
    int bk = (tid & 3) * 4;
    bool bok = (n0 + bn) < U_;

    unsigned long long acc2[8][2];
    #pragma unroll
    for (int i = 0; i < 8; i++) { acc2[i][0] = 0ull; acc2[i][1] = 0ull; }

    int kbeg = kz * 128;
    for (int k0 = kbeg; k0 < kbeg + 128; k0 += 16) {
        float4 a0 = *(const float4*)(g_wn + (m0 + am) * 256 + k0 + ak);
        float4 a1 = *(const float4*)(g_wn + (m0 + am) * 256 + k0 + ak + 4);
        float4 bv = make_float4(0.f, 0.f, 0.f, 0.f);
        if (bok) bv = *(const float4*)(g_un + (n0 + bn) * 256 + k0 + bk);
        __syncthreads();
        As[ak + 0][am] = a0.x; As[ak + 1][am] = a0.y;
        As[ak + 2][am] = a0.z; As[ak + 3][am] = a0.w;
        As[ak + 4][am] = a1.x; As[ak + 5][am] = a1.y;
        As[ak + 6][am] = a1.z; As[ak + 7][am] = a1.w;
        Bs[bk + 0][bn] = bv.x; Bs[bk + 1][bn] = bv.y;
        Bs[bk + 2][bn] = bv.z; Bs[bk + 3][bn] = bv.w;
        __syncthreads();
        #pragma unroll
        for (int kk = 0; kk < 16; kk++) {
            float4 av0 = *(const float4*)&As[kk][ty * 8];
            float4 av1 = *(const float4*)&As[kk][ty * 8 + 4];
            ulonglong2 bp = *(const ulonglong2*)&Bs[kk][tx * 4];
            unsigned long long d0 = pk2dup(av0.x), d1 = pk2dup(av0.y);
            unsigned long long d2 = pk2dup(av0.z), d3 = pk2dup(av0.w);
            unsigned long long d4 = pk2dup(av1.x), d5 = pk2dup(av1.y);
            unsigned long long d6 = pk2dup(av1.z), d7 = pk2dup(av1.w);
            ffma2(acc2[0][0], d0, bp.x); ffma2(acc2[0][1], d0, bp.y);
            ffma2(acc2[1][0], d1, bp.x); ffma2(acc2[1][1], d1, bp.y);
            ffma2(acc2[2][0], d2, bp.x); ffma2(acc2[2][1], d2, bp.y);
            ffma2(acc2[3][0], d3, bp.x); ffma2(acc2[3][1], d3, bp.y);
            ffma2(acc2[4][0], d4, bp.x); ffma2(acc2[4][1], d4, bp.y);
            ffma2(acc2[5][0], d5, bp.x); ffma2(acc2[5][1], d5, bp.y);
            ffma2(acc2[6][0], d6, bp.x); ffma2(acc2[6][1], d6, bp.y);
            ffma2(acc2[7][0], d7, bp.x); ffma2(acc2[7][1], d7, bp.y);
        }
    }
    #pragma unroll
    for (int i = 0; i < 8; i++) {
        int m = m0 + ty * 8 + i;
        #pragma unroll
        for (int j2 = 0; j2 < 2; j2++) {
            float2 c = unpk2(acc2[i][j2]);
            int n = n0 + tx * 4 + j2 * 2;
            if (n < U_)     dst[m * U_ + n] = c.x;
            if (n + 1 < U_) dst[m * U_ + n + 1] = c.y;
        }
    }
}

// ---------------------------------------------------------------------------
// Kernel 3 (hot): CTA per (vc, lt, b): 32 start positions (l = lt*32 + lane),
// 512 threads, 98.4KB smem -> 2 CTAs/SM (288 CTAs). Scalar scan.
//   S[u*41 + rr] = sim[b][l0+rr][u]  (K-halves summed; rows >= 64 are 0)
// Early-exit: lt=1 CTA with Lb < 36 has no valid span -> skip everything.
// Staging of one CTA overlaps scan of the co-resident CTA.
// ---------------------------------------------------------------------------
#define PB_SMEM (600 * 41 * 4)
#define VC_ 9
#define NPART_ (VC_ * 16)        // 144 partitions per (lt,b)
#define NCTA_PB (VC_ * 2 * 16)   // 288

template<int LEN>
__device__ __forceinline__ void scan_bucket(
        const uint4* __restrict__ seg, int lo, int hi,
        const float* __restrict__ Sl,
        unsigned long long mid, bool ok, float inv,
        unsigned long long& bestKey) {
    #pragma unroll 2
    for (int i = lo; i < hi; i++) {
        uint4 q0 = __ldg(&seg[2 * i]);
        unsigned u89 = 0, vv;
        if (LEN <= 7) {
            vv = q0.w >> 16;
        } else {
            uint4 q1 = __ldg(&seg[2 * i + 1]);
            u89 = q1.x; vv = q1.y;
        }
        float acc;
        unsigned u;
        u = q0.x & 0xFFFFu;                 acc  = Sl[u * 41 + 0];
        u = q0.x >> 16;                     acc += Sl[u * 41 + 1];
        u = q0.y & 0xFFFFu;                 acc += Sl[u * 41 + 2];
        u = q0.y >> 16;                     acc += Sl[u * 41 + 3];
        if (LEN > 4) { u = q0.z & 0xFFFFu;  acc += Sl[u * 41 + 4]; }
        if (LEN > 5) { u = q0.z >> 16;      acc += Sl[u * 41 + 5]; }
        if (LEN > 6) { u = q0.w & 0xFFFFu;  acc += Sl[u * 41 + 6]; }
        if (LEN > 7) { u = q0.w >> 16;      acc += Sl[u * 41 + 7]; }
        if (LEN > 8) { u = u89 & 0xFFFFu;   acc += Sl[u * 41 + 8]; }
        if (LEN > 9) { u = u89 >> 16;       acc += Sl[u * 41 + 9]; }
        float s = acc * inv;
        if (ok) {
            unsigned long long key = ((unsigned long long)f2mono(s) << 23) | mid
                                   | (unsigned long long)(16383u - vv);
            if (key > bestKey) bestKey = key;
        }
    }
}

__global__ void __launch_bounds__(512, 2) k_phaseB(const int* __restrict__ lengths,
                                                   float* __restrict__ out) {
    extern __shared__ float S[];
    __shared__ int cnt_s[8];
    int vc = blockIdx.x;   // 0..8
    int lt = blockIdx.y;   // 0..1
    int b  = blockIdx.z;   // 0..15
    int l0 = lt * 32;
    int Lb = __ldg(&lengths[b]);
    bool alive = (l0 + 4 <= Lb);     // any valid span starts in this l-half?

    if (alive) {
        if (threadIdx.x < 8) cnt_s[threadIdx.x] = g_cnt[threadIdx.x];
        // stage: S[u*41 + rr] = sum of the two K-halves (float2 over u)
        const float2* sA = (const float2*)(g_sim + b * 64 * U_);
        const float2* sB = (const float2*)(g_sim + 1024 * U_ + b * 64 * U_);
        for (int i = threadIdx.x; i < 300 * 41; i += 512) {
            int r = i / 300;
            int p = i - r * 300;
            int gl = l0 + r;
            float2 vv = make_float2(0.f, 0.f);
            if (gl < L_) {
                float2 a = sA[gl * 300 + p];
                float2 c = sB[gl * 300 + p];
                vv = make_float2(a.x + c.x, a.y + c.y);
            }
            int u = 2 * p;
            S[u * 41 + r]       = vv.x;
            S[(u + 1) * 41 + r] = vv.y;
        }
        __syncthreads();

        int warp = threadIdx.x >> 5;
        int lane = threadIdx.x & 31;
        int l = l0 + lane;
        const float* Sl = S + lane;
        int part = vc * 16 + warp;
        unsigned long long bestKey = ((unsigned long long)f2mono(NEGF) << 23);

        #define DO_BUCKET(LI, LEN)                                                      \
        if (l0 + LEN <= Lb) {                                                           \
            int n = cnt_s[LI];                                                          \
            int lo = (part * n) / NPART_;                                               \
            int hi = ((part + 1) * n) / NPART_;                                         \
            bool ok = (l + LEN <= Lb);                                                  \
            unsigned long long mid = ((unsigned long long)(511 - (l * E_ + LI)) << 14); \
            scan_bucket<LEN>(g_segB + LI * (V_ * 2), lo, hi, Sl, mid, ok,               \
                             1.0f / (float)LEN, bestKey);                               \
        }
        DO_BUCKET(0, 4) DO_BUCKET(1, 5) DO_BUCKET(2, 6) DO_BUCKET(3, 7)
        DO_BUCKET(4, 8) DO_BUCKET(5, 9) DO_BUCKET(6, 10)
        #undef DO_BUCKET

        #pragma unroll
        for (int o = 16; o; o >>= 1) {
            unsigned long long other = __shfl_down_sync(0xffffffffu, bestKey, o);
            if (other > bestKey) bestKey = other;
        }
        if (lane == 0) atomicMax(&g_keys[b], bestKey);
        __syncthreads();
    }

    // -------- fused epilogue: last CTA decodes + resets bucket counters -----
    __threadfence();
    __shared__ unsigned s_old;
    if (threadIdx.x == 0) s_old = atomicAdd(&g_done, 1u);
    __syncthreads();
    if (s_old == NCTA_PB - 1) {
        int t = threadIdx.x;
        if (t < B_) {
            unsigned long long k2 = atomicAdd(&g_keys[t], 0ull);
            int v = 16383 - (int)(k2 & 0x3FFFull);
            int f = 511 - (int)((k2 >> 14) & 0x1FFull);
            unsigned mono = (unsigned)(k2 >> 23);
            unsigned fb = (mono & 0x80000000u) ? (mono & 0x7FFFFFFFu) : ~mono;
            float score = __uint_as_float(fb);
            int ll = f / E_;
            int e = f - ll * E_;
            out[0 * B_ + t] = score;
            out[1 * B_ + t] = (float)ll;
            out[2 * B_ + t] = (float)(ll + e + 3);
            out[3 * B_ + t] = (score > 0.05f) ? 1.0f : 0.0f;
            out[4 * B_ + t] = (float)v;
        }
        if (t >= 32 && t < 40) g_cnt[t - 32] = 0;   // ready for next replay
    }
}

// ---------------------------------------------------------------------------
extern "C" void kernel_launch(void* const* d_in, const int* in_sizes, int n_in,
                              void* d_out, int out_size) {
    const float* x       = (const float*)d_in[0];
    const float* uf      = (const float*)d_in[1];
    const float* W       = (const float*)d_in[2];
    const int*   lengths = (const int*)d_in[3];
    const int*   segs    = (const int*)d_in[4];
    const int*   vlen    = (const int*)d_in[5];
    float* out = (float*)d_out;

    cudaFuncSetAttribute(k_phaseB, cudaFuncAttributeMaxDynamicSharedMemorySize, PB_SMEM);

    k_setup<<<SETUP_GRID, 256>>>(x, uf, W, segs, vlen);
    k_sim_gemm<<<dim3(10, 8, 2), 256>>>();
    k_phaseB<<<dim3(VC_, 2, B_), 512, PB_SMEM>>>(lengths, out);
}

// round 14
// speedup vs baseline: 1.0899x; 1.0899x over previous
#include <cuda_runtime.h>
#include <cstdint>

#define B_  16
#define L_  64
#define F_  60
#define D_  256
#define U_  600
#define V_  10000
#define E_  7
#define NEGF (-1e9f)
#define MROWS 1624   // 1024 word rows + 600 unit rows

// Scratch (device globals)
__device__ float g_wn[1024 * 256];           // raw (unnormalized) word reprs
__device__ float g_un[600 * 256];            // raw unit reprs
__device__ float g_nrm[MROWS];               // row sum-of-squares (reset each run)
__device__ float g_sim[2 * 1024 * 600];      // two K-halves, summed in phaseB staging
__device__ uint4 g_segB[7 * V_ * 2];         // length-bucketed vocab
__device__ int   g_cnt[8];                   // bucket counts (reset each run)
__device__ unsigned long long g_keys[16];
__device__ unsigned g_done;

// ---- f32x2 helpers ----
__device__ __forceinline__ void ffma2(unsigned long long& d, unsigned long long a, unsigned long long b) {
    asm("fma.rn.f32x2 %0, %1, %2, %0;" : "+l"(d) : "l"(a), "l"(b));
}
__device__ __forceinline__ void fadd2(unsigned long long& d, unsigned long long a) {
    asm("add.rn.f32x2 %0, %0, %1;" : "+l"(d) : "l"(a));
}
__device__ __forceinline__ void fmul2(unsigned long long& d, unsigned long long a) {
    asm("mul.rn.f32x2 %0, %0, %1;" : "+l"(d) : "l"(a));
}
__device__ __forceinline__ unsigned long long pk2dup(float a) {
    unsigned long long r; unsigned ai = __float_as_uint(a);
    asm("mov.b64 %0, {%1, %1};" : "=l"(r) : "r"(ai));
    return r;
}
__device__ __forceinline__ float2 unpk2(unsigned long long a) {
    unsigned lo, hi;
    asm("mov.b64 {%0, %1}, %2;" : "=r"(lo), "=r"(hi) : "l"(a));
    return make_float2(__uint_as_float(lo), __uint_as_float(hi));
}
__device__ __forceinline__ unsigned f2mono(float f) {
    unsigned b = __float_as_uint(f);
    return (b & 0x80000000u) ? ~b : (b | 0x80000000u);
}
__device__ __forceinline__ unsigned long long pack_key(float s, int f, int v) {
    return ((unsigned long long)f2mono(s) << 23)
         | ((unsigned long long)(511 - f) << 14)
         | (unsigned long long)(16383 - v);
}

// ---------------------------------------------------------------------------
// Kernel 1 (setup):
//   blocks  0..39 : vocab bucketing (+ key/done init)
//   blocks 40..91 : embed GEMM  R[M=1624, N=256] = [x;uf] @ W, K=60
//                   epilogue: raw store + per-row sumsq -> g_nrm (atomicAdd)
// ---------------------------------------------------------------------------
#define PBK_ 40
#define EMB_NT 4                   // 4 n-tiles of 64 (N=256)
#define EMB_MT 13                  // 13 m-tiles of 128 (M=1664 padded)
#define SETUP_GRID (PBK_ + EMB_NT * EMB_MT)   // 92
#define AS_STRIDE 132              // [60][132] floats (16B aligned rows)
#define BS_STRIDE 68               // [60][68]  floats
#define SETUP_SMEM ((60 * AS_STRIDE + 60 * BS_STRIDE) * 4)   // 48000 B

__global__ void __launch_bounds__(256) k_setup(const float* __restrict__ x,
                                               const float* __restrict__ uf,
                                               const float* __restrict__ W,
                                               const int* __restrict__ segs,
                                               const int* __restrict__ vlen) {
    extern __shared__ float SS[];
    int blk = blockIdx.x;
    int tid = threadIdx.x;
    if (blk >= PBK_) {
        // ---- embed GEMM tile ----
        float* As = SS;                        // [k][m] stride 132
        float* Bs = SS + 60 * AS_STRIDE;       // [k][n] stride 68
        int eb = blk - PBK_;
        int mt = eb >> 2, nt = eb & 3;
        int m0 = mt * 128, n0 = nt * 64;
        // load A rows (coalesced LDG; 4-way STS conflict acceptable)
        for (int i = tid; i < 128 * F_; i += 256) {
            int r = i / F_, f = i - (i / F_) * F_;
            int m = m0 + r; if (m > MROWS - 1) m = MROWS - 1;
            const float* srow = (m < 1024) ? (x + m * F_) : (uf + (m - 1024) * F_);
            As[f * AS_STRIDE + r] = srow[f];
        }
        // load B = W[:, n0:n0+64]
        for (int i = tid; i < F_ * 64; i += 256) {
            int f = i >> 6, j = i & 63;
            Bs[f * BS_STRIDE + j] = W[f * D_ + n0 + j];
        }
        __syncthreads();
        int tx = tid & 15, ty = tid >> 4;
        unsigned long long acc2[8][2];
        #pragma unroll
        for (int i = 0; i < 8; i++) { acc2[i][0] = 0ull; acc2[i][1] = 0ull; }
        #pragma unroll 4
        for (int kk = 0; kk < F_; kk++) {
            float4 av0 = *(const float4*)&As[kk * AS_STRIDE + ty * 8];
            float4 av1 = *(const float4*)&As[kk * AS_STRIDE + ty * 8 + 4];
            ulonglong2 bp = *(const ulonglong2*)&Bs[kk * BS_STRIDE + tx * 4];
            unsigned long long d0 = pk2dup(av0.x), d1 = pk2dup(av0.y);
            unsigned long long d2 = pk2dup(av0.z), d3 = pk2dup(av0.w);
            unsigned long long d4 = pk2dup(av1.x), d5 = pk2dup(av1.y);
            unsigned long long d6 = pk2dup(av1.z), d7 = pk2dup(av1.w);
            ffma2(acc2[0][0], d0, bp.x); ffma2(acc2[0][1], d0, bp.y);
            ffma2(acc2[1][0], d1, bp.x); ffma2(acc2[1][1], d1, bp.y);
            ffma2(acc2[2][0], d2, bp.x); ffma2(acc2[2][1], d2, bp.y);
            ffma2(acc2[3][0], d3, bp.x); ffma2(acc2[3][1], d3, bp.y);
            ffma2(acc2[4][0], d4, bp.x); ffma2(acc2[4][1], d4, bp.y);
            ffma2(acc2[5][0], d5, bp.x); ffma2(acc2[5][1], d5, bp.y);
            ffma2(acc2[6][0], d6, bp.x); ffma2(acc2[6][1], d6, bp.y);
            ffma2(acc2[7][0], d7, bp.x); ffma2(acc2[7][1], d7, bp.y);
        }
        // epilogue: raw stores + per-row sumsq
        #pragma unroll
        for (int i = 0; i < 8; i++) {
            int m = m0 + ty * 8 + i;
            float2 c0 = unpk2(acc2[i][0]);
            float2 c1 = unpk2(acc2[i][1]);
            float ss = c0.x * c0.x + c0.y * c0.y + c1.x * c1.x + c1.y * c1.y;
            #pragma unroll
            for (int o = 1; o < 16; o <<= 1) ss += __shfl_xor_sync(0xffffffffu, ss, o);
            if (m < MROWS) {
                float* drow = (m < 1024) ? (g_wn + m * D_) : (g_un + (m - 1024) * D_);
                int n = n0 + tx * 4;
                drow[n]     = c0.x;
                drow[n + 1] = c0.y;
                drow[n + 2] = c1.x;
                drow[n + 3] = c1.y;
                if (tx == 0) atomicAdd(&g_nrm[m], ss);
            }
        }
    } else {
        // ---- bucket vocab by length: block-aggregated atomics ----
        __shared__ int blkCnt[8];
        __shared__ int blkBase[8];
        int pb = blk;
        int d = tid;
        int v = pb * 256 + d;
        bool act = v < V_;
        if (d < 8) blkCnt[d] = 0;
        __syncthreads();
        int len = act ? vlen[v] : 11;
        int idx = act ? (len - 4) : 7;
        int lane = d & 31;
        unsigned mask = __match_any_sync(0xffffffffu, idx);
        int leader = __ffs(mask) - 1;
        int prior = __popc(mask & ((1u << lane) - 1));
        int wbase = 0;
        if (lane == leader) wbase = atomicAdd(&blkCnt[idx], __popc(mask));
        wbase = __shfl_sync(mask, wbase, leader);
        int local = wbase + prior;
        __syncthreads();
        if (d < 8) blkBase[d] = atomicAdd(&g_cnt[d], blkCnt[d]);
        __syncthreads();
        if (act) {
            unsigned w[5];
            #pragma unroll
            for (int p = 0; p < 5; p++) {
                unsigned lo = (unsigned)segs[v * 10 + 2 * p];
                unsigned hi = (unsigned)segs[v * 10 + 2 * p + 1];
                w[p] = (lo & 0xFFFFu) | (hi << 16);
            }
            if (len <= 7) w[3] = (w[3] & 0xFFFFu) | ((unsigned)v << 16);
            int slot = idx * V_ + blkBase[idx] + local;
            g_segB[slot * 2]     = make_uint4(w[0], w[1], w[2], w[3]);
            g_segB[slot * 2 + 1] = make_uint4(w[4], (unsigned)v, 0u, 0u);
        }
        if (pb == 0) {
            if (d >= 32 && d < 48) g_keys[d - 32] = pack_key(NEGF, 0, 0);
            if (d == 63) g_done = 0u;
        }
    }
}

// ---------------------------------------------------------------------------
// Kernel 2: sim = wr @ ur^T scaled by 1/(|wr|+eps)/(|ur|+eps) in the epilogue.
// 128x64 tile, 256 threads, 8x4 per thread, FFMA2, K split in halves.
// grid = (10, 8, 2) = 160 CTAs.
// ---------------------------------------------------------------------------
__global__ void __launch_bounds__(256) k_sim_gemm() {
    __shared__ float As[16][128];
    __shared__ float Bs[16][64];
    int tid = threadIdx.x;
    int n0 = blockIdx.x * 64;
    int m0 = blockIdx.y * 128;
    int kz = blockIdx.z;
    float* dst = g_sim + kz * (1024 * 600);
    int tx = tid & 15;
    int ty = tid >> 4;
    int am = tid >> 1;
    int ak = (tid & 1) * 8;
    int bn = tid >> 2;
    int bk = (tid & 3) * 4;
    bool bok = (n0 + bn) < U_;

    unsigned long long acc2[8][2];
    #pragma unroll
    for (int i = 0; i < 8; i++) { acc2[i][0] = 0ull; acc2[i][1] = 0ull; }

    int kbeg = kz * 128;
    for (int k0 = kbeg; k0 < kbeg + 128; k0 += 16) {
        float4 a0 = *(const float4*)(g_wn + (m0 + am) * 256 + k0 + ak);
        float4 a1 = *(const float4*)(g_wn + (m0 + am) * 256 + k0 + ak + 4);
        float4 bv = make_float4(0.f, 0.f, 0.f, 0.f);
        if (bok) bv = *(const float4*)(g_un + (n0 + bn) * 256 + k0 + bk);
        __syncthreads();
        As[ak + 0][am] = a0.x; As[ak + 1][am] = a0.y;
        As[ak + 2][am] = a0.z; As[ak + 3][am] = a0.w;
        As[ak + 4][am] = a1.x; As[ak + 5][am] = a1.y;
        As[ak + 6][am] = a1.z; As[ak + 7][am] = a1.w;
        Bs[bk + 0][bn] = bv.x; Bs[bk + 1][bn] = bv.y;
        Bs[bk + 2][bn] = bv.z; Bs[bk + 3][bn] = bv.w;
        __syncthreads();
        #pragma unroll
        for (int kk = 0; kk < 16; kk++) {
            float4 av0 = *(const float4*)&As[kk][ty * 8];
            float4 av1 = *(const float4*)&As[kk][ty * 8 + 4];
            ulonglong2 bp = *(const ulonglong2*)&Bs[kk][tx * 4];
            unsigned long long d0 = pk2dup(av0.x), d1 = pk2dup(av0.y);
            unsigned long long d2 = pk2dup(av0.z), d3 = pk2dup(av0.w);
            unsigned long long d4 = pk2dup(av1.x), d5 = pk2dup(av1.y);
            unsigned long long d6 = pk2dup(av1.z), d7 = pk2dup(av1.w);
            ffma2(acc2[0][0], d0, bp.x); ffma2(acc2[0][1], d0, bp.y);
            ffma2(acc2[1][0], d1, bp.x); ffma2(acc2[1][1], d1, bp.y);
            ffma2(acc2[2][0], d2, bp.x); ffma2(acc2[2][1], d2, bp.y);
            ffma2(acc2[3][0], d3, bp.x); ffma2(acc2[3][1], d3, bp.y);
            ffma2(acc2[4][0], d4, bp.x); ffma2(acc2[4][1], d4, bp.y);
            ffma2(acc2[5][0], d5, bp.x); ffma2(acc2[5][1], d5, bp.y);
            ffma2(acc2[6][0], d6, bp.x); ffma2(acc2[6][1], d6, bp.y);
            ffma2(acc2[7][0], d7, bp.x); ffma2(acc2[7][1], d7, bp.y);
        }
    }
    // epilogue: cosine scaling
    float invm[8];
    #pragma unroll
    for (int i = 0; i < 8; i++) {
        float s2 = __ldg(&g_nrm[m0 + ty * 8 + i]);
        invm[i] = 1.0f / (sqrtf(s2) + 1e-8f);
    }
    float invn[4];
    #pragma unroll
    for (int j = 0; j < 4; j++) {
        int n = n0 + tx * 4 + j;
        invn[j] = (n < U_) ? 1.0f / (sqrtf(__ldg(&g_nrm[1024 + n])) + 1e-8f) : 0.f;
    }
    #pragma unroll
    for (int i = 0; i < 8; i++) {
        int m = m0 + ty * 8 + i;
        #pragma unroll
        for (int j2 = 0; j2 < 2; j2++) {
            float2 c = unpk2(acc2[i][j2]);
            int n = n0 + tx * 4 + j2 * 2;
            if (n < U_)     dst[m * U_ + n]     = c.x * invm[i] * invn[j2 * 2];
            if (n + 1 < U_) dst[m * U_ + n + 1] = c.y * invm[i] * invn[j2 * 2 + 1];
        }
    }
}

// ---------------------------------------------------------------------------
// Kernel 3 (hot, R11 design): CTA per (vc, b), 1024 threads (32 warps).
// Smem: P[u*41 + r] = { sim[b][r][u], sim[b][r+32][u] }, rows>=64 are 0.
// Lanes = 32 start positions; both 32-l halves accumulated via f32x2.
// ---------------------------------------------------------------------------
#define PB_SMEM (600 * 41 * 8)
#define VC_ 9
#define NPART_ (VC_ * 32)       // 288 vocab partitions
#define NCTA_PB (VC_ * 16)      // 144

template<int LEN>
__device__ __forceinline__ void scan_bucket(
        const uint4* __restrict__ seg, int lo, int hi,
        const float2* __restrict__ Pl,
        unsigned long long midLo, unsigned long long midHi,
        bool okLo, bool okHi, float inv,
        unsigned long long& bestKey) {
    unsigned long long inv2 = pk2dup(inv);
    #pragma unroll 2
    for (int i = lo; i < hi; i++) {
        uint4 q0 = __ldg(&seg[2 * i]);
        unsigned u89 = 0, vv;
        if (LEN <= 7) {
            vv = q0.w >> 16;
        } else {
            uint4 q1 = __ldg(&seg[2 * i + 1]);
            u89 = q1.x; vv = q1.y;
        }
        unsigned long long acc;
        unsigned u;
        u = q0.x & 0xFFFFu;                 acc = *(const unsigned long long*)(Pl + u * 41 + 0);
        u = q0.x >> 16;                     fadd2(acc, *(const unsigned long long*)(Pl + u * 41 + 1));
        u = q0.y & 0xFFFFu;                 fadd2(acc, *(const unsigned long long*)(Pl + u * 41 + 2));
        u = q0.y >> 16;                     fadd2(acc, *(const unsigned long long*)(Pl + u * 41 + 3));
        if (LEN > 4) { u = q0.z & 0xFFFFu;  fadd2(acc, *(const unsigned long long*)(Pl + u * 41 + 4)); }
        if (LEN > 5) { u = q0.z >> 16;      fadd2(acc, *(const unsigned long long*)(Pl + u * 41 + 5)); }
        if (LEN > 6) { u = q0.w & 0xFFFFu;  fadd2(acc, *(const unsigned long long*)(Pl + u * 41 + 6)); }
        if (LEN > 7) { u = q0.w >> 16;      fadd2(acc, *(const unsigned long long*)(Pl + u * 41 + 7)); }
        if (LEN > 8) { u = u89 & 0xFFFFu;   fadd2(acc, *(const unsigned long long*)(Pl + u * 41 + 8)); }
        if (LEN > 9) { u = u89 >> 16;       fadd2(acc, *(const unsigned long long*)(Pl + u * 41 + 9)); }
        fmul2(acc, inv2);
        float2 s = unpk2(acc);
        unsigned long long vterm = (unsigned long long)(16383u - vv);
        if (okLo) {
            unsigned long long key = ((unsigned long long)f2mono(s.x) << 23) | midLo | vterm;
            if (key > bestKey) bestKey = key;
        }
        if (okHi) {
            unsigned long long key = ((unsigned long long)f2mono(s.y) << 23) | midHi | vterm;
            if (key > bestKey) bestKey = key;
        }
    }
}

__global__ void __launch_bounds__(1024, 1) k_phaseB(const int* __restrict__ lengths,
                                                    float* __restrict__ out) {
    extern __shared__ float2 P[];
    __shared__ int cnt_s[8];
    int vc = blockIdx.x;   // 0..8
    int b  = blockIdx.y;   // 0..15
    if (threadIdx.x < 8) cnt_s[threadIdx.x] = g_cnt[threadIdx.x];
    const float* sA = g_sim + b * 64 * U_;
    const float* sB = sA + 1024 * U_;
    for (int i = threadIdx.x; i < U_ * 41; i += 1024) {
        int r = i / U_;
        int u = i - r * U_;
        float lo = sA[r * U_ + u] + sB[r * U_ + u];
        float hi = (r < 32) ? (sA[(r + 32) * U_ + u] + sB[(r + 32) * U_ + u]) : 0.f;
        P[u * 41 + r] = make_float2(lo, hi);
    }
    __syncthreads();

    int warp = threadIdx.x >> 5;
    int lane = threadIdx.x & 31;
    int Lb = __ldg(&lengths[b]);
    const float2* Pl = P + lane;
    int part = vc * 32 + warp;
    unsigned long long bestKey = ((unsigned long long)f2mono(NEGF) << 23);

    #define DO_BUCKET(LI, LEN)                                                          \
    if (LEN <= Lb) {                                                                    \
        int n = cnt_s[LI];                                                              \
        int lo = (part * n) / NPART_;                                                   \
        int hi = ((part + 1) * n) / NPART_;                                             \
        bool okLo = lane + LEN <= Lb;                                                   \
        bool okHi = lane + 32 + LEN <= Lb;                                              \
        unsigned long long midLo = ((unsigned long long)(511 - (lane * E_ + LI)) << 14);\
        unsigned long long midHi = ((unsigned long long)(511 - ((lane + 32) * E_ + LI)) << 14);\
        scan_bucket<LEN>(g_segB + LI * (V_ * 2), lo, hi, Pl, midLo, midHi, okLo, okHi,  \
                         1.0f / (float)LEN, bestKey);                                   \
    }
    DO_BUCKET(0, 4) DO_BUCKET(1, 5) DO_BUCKET(2, 6) DO_BUCKET(3, 7)
    DO_BUCKET(4, 8) DO_BUCKET(5, 9) DO_BUCKET(6, 10)
    #undef DO_BUCKET

    #pragma unroll
    for (int o = 16; o; o >>= 1) {
        unsigned long long other = __shfl_down_sync(0xffffffffu, bestKey, o);
        if (other > bestKey) bestKey = other;
    }
    if (lane == 0) atomicMax(&g_keys[b], bestKey);

    // -------- fused epilogue: last CTA decodes + resets counters/norms ------
    __syncthreads();
    __threadfence();
    __shared__ unsigned s_old;
    if (threadIdx.x == 0) s_old = atomicAdd(&g_done, 1u);
    __syncthreads();
    if (s_old == NCTA_PB - 1) {
        int t = threadIdx.x;
        if (t < B_) {
            unsigned long long k2 = atomicAdd(&g_keys[t], 0ull);
            int v = 16383 - (int)(k2 & 0x3FFFull);
            int f = 511 - (int)((k2 >> 14) & 0x1FFull);
            unsigned mono = (unsigned)(k2 >> 23);
            unsigned fb = (mono & 0x80000000u) ? (mono & 0x7FFFFFFFu) : ~mono;
            float score = __uint_as_float(fb);
            int ll = f / E_;
            int e = f - ll * E_;
            out[0 * B_ + t] = score;
            out[1 * B_ + t] = (float)ll;
            out[2 * B_ + t] = (float)(ll + e + 3);
            out[3 * B_ + t] = (score > 0.05f) ? 1.0f : 0.0f;
            out[4 * B_ + t] = (float)v;
        }
        if (t >= 32 && t < 40) g_cnt[t - 32] = 0;            // for next replay
        for (int i = t; i < MROWS; i += 1024) g_nrm[i] = 0.f; // for next replay
    }
}

// ---------------------------------------------------------------------------
extern "C" void kernel_launch(void* const* d_in, const int* in_sizes, int n_in,
                              void* d_out, int out_size) {
    const float* x       = (const float*)d_in[0];
    const float* uf      = (const float*)d_in[1];
    const float* W       = (const float*)d_in[2];
    const int*   lengths = (const int*)d_in[3];
    const int*   segs    = (const int*)d_in[4];
    const int*   vlen    = (const int*)d_in[5];
    float* out = (float*)d_out;

    cudaFuncSetAttribute(k_setup, cudaFuncAttributeMaxDynamicSharedMemorySize, SETUP_SMEM);
    cudaFuncSetAttribute(k_phaseB, cudaFuncAttributeMaxDynamicSharedMemorySize, PB_SMEM);

    k_setup<<<SETUP_GRID, 256, SETUP_SMEM>>>(x, uf, W, segs, vlen);
    k_sim_gemm<<<dim3(10, 8, 2), 256>>>();
    k_phaseB<<<dim3(VC_, B_), 1024, PB_SMEM>>>(lengths, out);
}

// round 15
// speedup vs baseline: 1.3215x; 1.2125x over previous
#include <cuda_runtime.h>
#include <cstdint>

#define B_  16
#define L_  64
#define F_  60
#define U_  600
#define V_  10000
#define E_  7
#define NEGF (-1e9f)

// Scratch (device globals)
__device__ float g_G[64 * 64];            // G = W W^T, padded to 64x64 (pads = 0)
__device__ float g_ugT[64 * 640];         // scaled unit reprs, TRANSPOSED [k][u] (pads 0)
__device__ float g_inx[1024];             // per word-row 1/(|xW|+eps)
__device__ float g_sim[1024 * 600];       // cosine sim [B*L][U]
__device__ uint4 g_segB[7 * V_ * 2];      // length-bucketed vocab
__device__ int   g_cnt[8];                // bucket counts (reset by phaseB epilogue)
__device__ unsigned long long g_keys[16];
__device__ unsigned g_done;

// ---- f32x2 helpers ----
__device__ __forceinline__ void ffma2(unsigned long long& d, unsigned long long a, unsigned long long b) {
    asm("fma.rn.f32x2 %0, %1, %2, %0;" : "+l"(d) : "l"(a), "l"(b));
}
__device__ __forceinline__ void fadd2(unsigned long long& d, unsigned long long a) {
    asm("add.rn.f32x2 %0, %0, %1;" : "+l"(d) : "l"(a));
}
__device__ __forceinline__ void fmul2(unsigned long long& d, unsigned long long a) {
    asm("mul.rn.f32x2 %0, %0, %1;" : "+l"(d) : "l"(a));
}
__device__ __forceinline__ unsigned long long pk2dup(float a) {
    unsigned long long r; unsigned ai = __float_as_uint(a);
    asm("mov.b64 %0, {%1, %1};" : "=l"(r) : "r"(ai));
    return r;
}
__device__ __forceinline__ float2 unpk2(unsigned long long a) {
    unsigned lo, hi;
    asm("mov.b64 {%0, %1}, %2;" : "=r"(lo), "=r"(hi) : "l"(a));
    return make_float2(__uint_as_float(lo), __uint_as_float(hi));
}
__device__ __forceinline__ unsigned f2mono(float f) {
    unsigned b = __float_as_uint(f);
    return (b & 0x80000000u) ? ~b : (b | 0x80000000u);
}
__device__ __forceinline__ unsigned long long pack_key(float s, int f, int v) {
    return ((unsigned long long)f2mono(s) << 23)
         | ((unsigned long long)(511 - f) << 14)
         | (unsigned long long)(16383 - v);
}

// ---------------------------------------------------------------------------
// Kernel 1 (setup): blocks 0..39 bucket vocab; blocks 40..99 compute G rows.
// ---------------------------------------------------------------------------
#define PBK_ 40
#define SETUP_GRID (PBK_ + 60)   // 100

__global__ void __launch_bounds__(256) k_setup(const float* __restrict__ W,
                                               const int* __restrict__ segs,
                                               const int* __restrict__ vlen) {
    int blk = blockIdx.x;
    int tid = threadIdx.x;
    if (blk >= PBK_) {
        // ---- G[i][:] : dot of W row i with all rows j (K=256) ----
        int i = blk - PBK_;
        int j = tid >> 2;        // 0..63
        int ks = tid & 3;        // quarter of K
        float acc0 = 0.f, acc1 = 0.f;
        if (j < F_) {
            const float* wi = W + i * 256 + ks * 64;
            const float* wj = W + j * 256 + ks * 64;
            #pragma unroll 8
            for (int k = 0; k < 64; k += 2) {
                acc0 = fmaf(__ldg(&wi[k]),     __ldg(&wj[k]),     acc0);
                acc1 = fmaf(__ldg(&wi[k + 1]), __ldg(&wj[k + 1]), acc1);
            }
        }
        float acc = acc0 + acc1;
        acc += __shfl_xor_sync(0xffffffffu, acc, 1);
        acc += __shfl_xor_sync(0xffffffffu, acc, 2);
        if (ks == 0) g_G[i * 64 + j] = (j < F_) ? acc : 0.f;
    } else {
        // ---- bucket vocab by length: block-aggregated atomics ----
        __shared__ int blkCnt[8];
        __shared__ int blkBase[8];
        int pb = blk;
        int d = tid;
        int v = pb * 256 + d;
        bool act = v < V_;
        if (d < 8) blkCnt[d] = 0;
        __syncthreads();
        int len = act ? vlen[v] : 11;
        int idx = act ? (len - 4) : 7;
        int lane = d & 31;
        unsigned mask = __match_any_sync(0xffffffffu, idx);
        int leader = __ffs(mask) - 1;
        int prior = __popc(mask & ((1u << lane) - 1));
        int wbase = 0;
        if (lane == leader) wbase = atomicAdd(&blkCnt[idx], __popc(mask));
        wbase = __shfl_sync(mask, wbase, leader);
        int local = wbase + prior;
        __syncthreads();
        if (d < 8) blkBase[d] = atomicAdd(&g_cnt[d], blkCnt[d]);
        __syncthreads();
        if (act) {
            unsigned w[5];
            #pragma unroll
            for (int p = 0; p < 5; p++) {
                unsigned lo = (unsigned)segs[v * 10 + 2 * p];
                unsigned hi = (unsigned)segs[v * 10 + 2 * p + 1];
                w[p] = (lo & 0xFFFFu) | (hi << 16);
            }
            if (len <= 7) w[3] = (w[3] & 0xFFFFu) | ((unsigned)v << 16);
            int slot = idx * V_ + blkBase[idx] + local;
            g_segB[slot * 2]     = make_uint4(w[0], w[1], w[2], w[3]);
            g_segB[slot * 2 + 1] = make_uint4(w[4], (unsigned)v, 0u, 0u);
        }
        if (pb == 0) {
            if (d >= 32 && d < 48) g_keys[d - 32] = pack_key(NEGF, 0, 0);
            if (d == 63) g_done = 0u;
        }
    }
}

// ---------------------------------------------------------------------------
// Kernel 2 (rowops): 8 rows/block over [x;uf] (1624 rows -> 203 blocks).
//   R = row @ G  (K=60, N=64-padded); nrm = dot(row, R).
//   Word rows  (m < 1024): store g_inx[m] = 1/(sqrt(nrm)+eps).
//   Unit rows: store g_ugT[k][u] = R[k] * 1/(sqrt(nrm)+eps)  (transposed).
// ---------------------------------------------------------------------------
#define ROP_GRID 203

__global__ void __launch_bounds__(256) k_rowops(const float* __restrict__ x,
                                                const float* __restrict__ uf) {
    __shared__ float feat[8][64];
    __shared__ float sp0[8], sp1[8], sinv[8];
    int blk = blockIdx.x;
    int tid = threadIdx.x;
    int m0 = blk * 8;
    bool isWord = m0 < 1024;
    const float* src = isWord ? (x + m0 * F_) : (uf + (m0 - 1024) * F_);
    for (int i = tid; i < 8 * 64; i += 256) {
        int r = i >> 6, j = i & 63;
        feat[r][j] = (j < F_) ? src[r * F_ + j] : 0.f;
    }
    __syncthreads();
    int j = tid & 63;
    int rr = tid >> 6;          // rows rr and rr+4
    float acc0 = 0.f, acc1 = 0.f;
    #pragma unroll 10
    for (int f = 0; f < F_; f++) {
        float g = __ldg(&g_G[f * 64 + j]);
        acc0 = fmaf(feat[rr][f],     g, acc0);
        acc1 = fmaf(feat[rr + 4][f], g, acc1);
    }
    // nrm = dot(feat_row, R_row)  (feat zero-padded for j>=60)
    float p0 = feat[rr][j]     * acc0;
    float p1 = feat[rr + 4][j] * acc1;
    #pragma unroll
    for (int o = 16; o; o >>= 1) {
        p0 += __shfl_down_sync(0xffffffffu, p0, o);
        p1 += __shfl_down_sync(0xffffffffu, p1, o);
    }
    int w = tid >> 5;            // = rr*2 + (j>>5)
    if ((tid & 31) == 0) { sp0[w] = p0; sp1[w] = p1; }
    __syncthreads();
    if (tid < 8) {
        float nrm = (tid < 4) ? (sp0[tid * 2] + sp0[tid * 2 + 1])
                              : (sp1[(tid - 4) * 2] + sp1[(tid - 4) * 2 + 1]);
        sinv[tid] = 1.0f / (sqrtf(fmaxf(nrm, 0.f)) + 1e-8f);
    }
    __syncthreads();
    if (isWord) {
        if (tid < 8) g_inx[m0 + tid] = sinv[tid];
    } else {
        int u0 = m0 - 1024;
        g_ugT[j * 640 + u0 + rr]     = acc0 * sinv[rr];
        g_ugT[j * 640 + u0 + rr + 4] = acc1 * sinv[rr + 4];
    }
}

// ---------------------------------------------------------------------------
// Kernel 3: sim = x @ Ug_scaled^T * invx.  M=1024, N=600(pad 640), K=60.
// 64x64 tile, 256 threads, 4x4 per thread, one K pass.  grid = (10,16) = 160.
// ---------------------------------------------------------------------------
__global__ void __launch_bounds__(256) k_sim(const float* __restrict__ x) {
    __shared__ float As[64 * 68];   // [m][k] row-major, stride 68
    __shared__ float Bs[64 * 64];   // [k][n]
    int tid = threadIdx.x;
    int n0 = blockIdx.x * 64;
    int m0 = blockIdx.y * 64;
    int tx = tid & 15, ty = tid >> 4;
    // stage A: 64 rows x 15 float4 (x rows are 60 floats, 16B-aligned)
    for (int i = tid; i < 960; i += 256) {
        int m = i / 15, q = i - (i / 15) * 15;
        *(float4*)&As[m * 68 + q * 4] = *(const float4*)(x + (m0 + m) * F_ + q * 4);
    }
    // stage B: 64 k-rows x 16 float4 from transposed scaled unit reprs
    for (int i = tid; i < 1024; i += 256) {
        int k = i >> 4, q = i & 15;
        *(float4*)&Bs[k * 64 + q * 4] = *(const float4*)&g_ugT[k * 640 + n0 + q * 4];
    }
    __syncthreads();
    unsigned long long acc2[4][2];
    #pragma unroll
    for (int i = 0; i < 4; i++) { acc2[i][0] = 0ull; acc2[i][1] = 0ull; }
    #pragma unroll 4
    for (int kk = 0; kk < F_; kk++) {
        ulonglong2 bp = *(const ulonglong2*)&Bs[kk * 64 + tx * 4];
        // scalar A reads: banks (4m+kk)%32, 8 distinct per warp -> conflict-free
        unsigned long long d0 = pk2dup(As[(ty * 4 + 0) * 68 + kk]);
        unsigned long long d1 = pk2dup(As[(ty * 4 + 1) * 68 + kk]);
        unsigned long long d2 = pk2dup(As[(ty * 4 + 2) * 68 + kk]);
        unsigned long long d3 = pk2dup(As[(ty * 4 + 3) * 68 + kk]);
        ffma2(acc2[0][0], d0, bp.x); ffma2(acc2[0][1], d0, bp.y);
        ffma2(acc2[1][0], d1, bp.x); ffma2(acc2[1][1], d1, bp.y);
        ffma2(acc2[2][0], d2, bp.x); ffma2(acc2[2][1], d2, bp.y);
        ffma2(acc2[3][0], d3, bp.x); ffma2(acc2[3][1], d3, bp.y);
    }
    #pragma unroll
    for (int i = 0; i < 4; i++) {
        int m = m0 + ty * 4 + i;
        float inv = __ldg(&g_inx[m]);
        #pragma unroll
        for (int j2 = 0; j2 < 2; j2++) {
            float2 c = unpk2(acc2[i][j2]);
            int n = n0 + tx * 4 + j2 * 2;
            if (n < U_)     g_sim[m * U_ + n]     = c.x * inv;
            if (n + 1 < U_) g_sim[m * U_ + n + 1] = c.y * inv;
        }
    }
}

// ---------------------------------------------------------------------------
// Kernel 4 (hot, R11 design): CTA per (vc, b), 1024 threads (32 warps).
// Smem: P[u*41 + r] = { sim[b][r][u], sim[b][r+32][u] } (single sim buffer).
// Lanes = 32 start positions; both 32-l halves accumulated via f32x2.
// ---------------------------------------------------------------------------
#define PB_SMEM (600 * 41 * 8)
#define VC_ 9
#define NPART_ (VC_ * 32)       // 288 vocab partitions
#define NCTA_PB (VC_ * 16)      // 144

template<int LEN>
__device__ __forceinline__ void scan_bucket(
        const uint4* __restrict__ seg, int lo, int hi,
        const float2* __restrict__ Pl,
        unsigned long long midLo, unsigned long long midHi,
        bool okLo, bool okHi, float inv,
        unsigned long long& bestKey) {
    unsigned long long inv2 = pk2dup(inv);
    #pragma unroll 2
    for (int i = lo; i < hi; i++) {
        uint4 q0 = __ldg(&seg[2 * i]);
        unsigned u89 = 0, vv;
        if (LEN <= 7) {
            vv = q0.w >> 16;
        } else {
            uint4 q1 = __ldg(&seg[2 * i + 1]);
            u89 = q1.x; vv = q1.y;
        }
        unsigned long long acc;
        unsigned u;
        u = q0.x & 0xFFFFu;                 acc = *(const unsigned long long*)(Pl + u * 41 + 0);
        u = q0.x >> 16;                     fadd2(acc, *(const unsigned long long*)(Pl + u * 41 + 1));
        u = q0.y & 0xFFFFu;                 fadd2(acc, *(const unsigned long long*)(Pl + u * 41 + 2));
        u = q0.y >> 16;                     fadd2(acc, *(const unsigned long long*)(Pl + u * 41 + 3));
        if (LEN > 4) { u = q0.z & 0xFFFFu;  fadd2(acc, *(const unsigned long long*)(Pl + u * 41 + 4)); }
        if (LEN > 5) { u = q0.z >> 16;      fadd2(acc, *(const unsigned long long*)(Pl + u * 41 + 5)); }
        if (LEN > 6) { u = q0.w & 0xFFFFu;  fadd2(acc, *(const unsigned long long*)(Pl + u * 41 + 6)); }
        if (LEN > 7) { u = q0.w >> 16;      fadd2(acc, *(const unsigned long long*)(Pl + u * 41 + 7)); }
        if (LEN > 8) { u = u89 & 0xFFFFu;   fadd2(acc, *(const unsigned long long*)(Pl + u * 41 + 8)); }
        if (LEN > 9) { u = u89 >> 16;       fadd2(acc, *(const unsigned long long*)(Pl + u * 41 + 9)); }
        fmul2(acc, inv2);
        float2 s = unpk2(acc);
        unsigned long long vterm = (unsigned long long)(16383u - vv);
        if (okLo) {
            unsigned long long key = ((unsigned long long)f2mono(s.x) << 23) | midLo | vterm;
            if (key > bestKey) bestKey = key;
        }
        if (okHi) {
            unsigned long long key = ((unsigned long long)f2mono(s.y) << 23) | midHi | vterm;
            if (key > bestKey) bestKey = key;
        }
    }
}

__global__ void __launch_bounds__(1024, 1) k_phaseB(const int* __restrict__ lengths,
                                                    float* __restrict__ out) {
    extern __shared__ float2 P[];
    __shared__ int cnt_s[8];
    int vc = blockIdx.x;   // 0..8
    int b  = blockIdx.y;   // 0..15
    if (threadIdx.x < 8) cnt_s[threadIdx.x] = g_cnt[threadIdx.x];
    const float* sA = g_sim + b * 64 * U_;
    for (int i = threadIdx.x; i < U_ * 41; i += 1024) {
        int r = i / U_;
        int u = i - r * U_;
        float lo = __ldg(&sA[r * U_ + u]);
        float hi = (r < 32) ? __ldg(&sA[(r + 32) * U_ + u]) : 0.f;
        P[u * 41 + r] = make_float2(lo, hi);
    }
    __syncthreads();

    int warp = threadIdx.x >> 5;
    int lane = threadIdx.x & 31;
    int Lb = __ldg(&lengths[b]);
    const float2* Pl = P + lane;
    int part = vc * 32 + warp;
    unsigned long long bestKey = ((unsigned long long)f2mono(NEGF) << 23);

    #define DO_BUCKET(LI, LEN)                                                          \
    if (LEN <= Lb) {                                                                    \
        int n = cnt_s[LI];                                                              \
        int lo = (part * n) / NPART_;                                                   \
        int hi = ((part + 1) * n) / NPART_;                                             \
        bool okLo = lane + LEN <= Lb;                                                   \
        bool okHi = lane + 32 + LEN <= Lb;                                              \
        unsigned long long midLo = ((unsigned long long)(511 - (lane * E_ + LI)) << 14);\
        unsigned long long midHi = ((unsigned long long)(511 - ((lane + 32) * E_ + LI)) << 14);\
        scan_bucket<LEN>(g_segB + LI * (V_ * 2), lo, hi, Pl, midLo, midHi, okLo, okHi,  \
                         1.0f / (float)LEN, bestKey);                                   \
    }
    DO_BUCKET(0, 4) DO_BUCKET(1, 5) DO_BUCKET(2, 6) DO_BUCKET(3, 7)
    DO_BUCKET(4, 8) DO_BUCKET(5, 9) DO_BUCKET(6, 10)
    #undef DO_BUCKET

    #pragma unroll
    for (int o = 16; o; o >>= 1) {
        unsigned long long other = __shfl_down_sync(0xffffffffu, bestKey, o);
        if (other > bestKey) bestKey = other;
    }
    if (lane == 0) atomicMax(&g_keys[b], bestKey);

    // -------- fused epilogue: last CTA decodes + resets counters ------------
    __syncthreads();
    __threadfence();
    __shared__ unsigned s_old;
    if (threadIdx.x == 0) s_old = atomicAdd(&g_done, 1u);
    __syncthreads();
    if (s_old == NCTA_PB - 1) {
        int t = threadIdx.x;
        if (t < B_) {
            unsigned long long k2 = atomicAdd(&g_keys[t], 0ull);
            int v = 16383 - (int)(k2 & 0x3FFFull);
            int f = 511 - (int)((k2 >> 14) & 0x1FFull);
            unsigned mono = (unsigned)(k2 >> 23);
            unsigned fb = (mono & 0x80000000u) ? (mono & 0x7FFFFFFFu) : ~mono;
            float score = __uint_as_float(fb);
            int ll = f / E_;
            int e = f - ll * E_;
            out[0 * B_ + t] = score;
            out[1 * B_ + t] = (float)ll;
            out[2 * B_ + t] = (float)(ll + e + 3);
            out[3 * B_ + t] = (score > 0.05f) ? 1.0f : 0.0f;
            out[4 * B_ + t] = (float)v;
        }
        if (t >= 32 && t < 40) g_cnt[t - 32] = 0;   // ready for next replay
    }
}

// ---------------------------------------------------------------------------
extern "C" void kernel_launch(void* const* d_in, const int* in_sizes, int n_in,
                              void* d_out, int out_size) {
    const float* x       = (const float*)d_in[0];   // [16,64,60]
    const float* uf      = (const float*)d_in[1];   // [600,60]
    const float* W       = (const float*)d_in[2];   // [60,256]
    const int*   lengths = (const int*)d_in[3];     // [16]
    const int*   segs    = (const int*)d_in[4];     // [10000,10]
    const int*   vlen    = (const int*)d_in[5];     // [10000]
    float* out = (float*)d_out;

    cudaFuncSetAttribute(k_phaseB, cudaFuncAttributeMaxDynamicSharedMemorySize, PB_SMEM);

    k_setup<<<SETUP_GRID, 256>>>(W, segs, vlen);
    k_rowops<<<ROP_GRID, 256>>>(x, uf);
    k_sim<<<dim3(10, 16), 256>>>(x);
    k_phaseB<<<dim3(VC_, B_), 1024, PB_SMEM>>>(lengths, out);
}